// round 4
// baseline (speedup 1.0000x reference)
#include <cuda_runtime.h>
#include <math.h>

// ---------------- problem constants ----------------
#define Nn    20000
#define Ee    640000
#define Pp    27
#define Mm    5000
#define MAXNb 64
#define KIN   64
#define PIN   (Pp * KIN)      // 1728
#define R2c   0.01f
#define NC    512             // 8x8x8 spatial cells

// output section offsets (flattened float32 tuple concat)
#define SEC_X     0
#define SEC_COL   320000
#define SEC_ROW   640000
#define SEC_POS   960000
#define SEC_BATCH 975000
#define SEC_EA    980000

// ---------------- persistent device scratch ----------------
__device__ __align__(16) float4 g_pos4[Nn];   // x,y,z, |p|^2
__device__ int    g_idx[Mm];
__device__ int    g_selmap[Nn];
__device__ __align__(16) float g_acc[(size_t)(Mm + 16) * PIN];  // padded
// cell structures
__device__ int    g_pcell[Nn];
__device__ int    g_cellcnt[NC];
__device__ int    g_cellstart[NC + 1];
__device__ int    g_cellfill[NC];
__device__ __align__(16) float4 g_spos[Nn];   // cell-sorted: x,y,z, orig idx bits
// CSR edge structures
__device__ int    g_ecnt[Mm];
__device__ int    g_eoff[Mm];
__device__ int    g_efill[Mm];
__device__ int    g_elist[Ee];

// ---------------- prep (single block): pos4 + cell id + histogram ----------------
__global__ void __launch_bounds__(1024) prep1b_kernel(const float* __restrict__ pos) {
    int tid = threadIdx.x;
    if (tid < NC) g_cellcnt[tid] = 0;
    __syncthreads();
    for (int i = tid; i < Nn; i += 1024) {
        float x = pos[3 * i], y = pos[3 * i + 1], z = pos[3 * i + 2];
        float an = __fadd_rn(__fadd_rn(__fmul_rn(x, x), __fmul_rn(y, y)),
                             __fmul_rn(z, z));
        g_pos4[i] = make_float4(x, y, z, an);
        int cx = min((int)(x * 8.0f), 7);
        int cy = min((int)(y * 8.0f), 7);
        int cz = min((int)(z * 8.0f), 7);
        int cid = (cx << 6) | (cy << 3) | cz;
        g_pcell[i] = cid;
        atomicAdd(&g_cellcnt[cid], 1);
    }
}

__global__ void cell_scan_kernel() {
    __shared__ int sh[NC];
    int tid = threadIdx.x;
    int v = g_cellcnt[tid];
    sh[tid] = v;
    __syncthreads();
    for (int o = 1; o < NC; o <<= 1) {
        int t = (tid >= o) ? sh[tid - o] : 0;
        __syncthreads();
        sh[tid] += t;
        __syncthreads();
    }
    g_cellstart[tid + 1] = sh[tid];
    g_cellfill[tid] = sh[tid] - v;
    if (tid == 0) g_cellstart[0] = 0;
}

__global__ void cell_scatter_kernel(const float* __restrict__ pos) {
    int i = blockIdx.x * blockDim.x + threadIdx.x;
    if (i >= Nn) return;
    int cid = g_pcell[i];
    int off = atomicAdd(&g_cellfill[cid], 1);
    g_spos[off] = make_float4(pos[3 * i], pos[3 * i + 1], pos[3 * i + 2],
                              __int_as_float(i));
}

// ---------------- FPS: SINGLE WARP, exact cell pruning ----------------
#define OFF_CKEY   80000u
#define OFF_CUBP   84096u
#define OFF_WINPOS 86144u
#define OFF_CST    94336u
#define OFF_ACT    96388u
#define OFF_PKEY   98440u
#define OFF_PPOS   106896u
#define FPS_SMEM   123792u

__global__ void __launch_bounds__(32, 1) fps_kernel() {
    extern __shared__ unsigned char s_raw[];
    float*              s_mind   = (float*)(s_raw);
    unsigned long long* s_ckey   = (unsigned long long*)(s_raw + OFF_CKEY);
    float*              s_cubp   = (float*)(s_raw + OFF_CUBP);   // permuted
    float4*             s_winpos = (float4*)(s_raw + OFF_WINPOS);
    int*                s_cst    = (int*)(s_raw + OFF_CST);
    int*                s_act    = (int*)(s_raw + OFF_ACT);
    unsigned long long* s_pkey   = (unsigned long long*)(s_raw + OFF_PKEY);
    float4*             s_ppos   = (float4*)(s_raw + OFF_PPOS);

    const int lane = threadIdx.x;
    const unsigned FULL = 0xffffffffu;
    const float INF = __int_as_float(0x7f800000);
    const float4* __restrict__ sp = g_spos;

    for (int i = lane; i < Nn; i += 32) s_mind[i] = INF;
    for (int i = lane; i <= NC; i += 32) s_cst[i] = g_cellstart[i];
    __syncwarp();
    for (int c = lane; c < NC; c += 32) {
        bool ne = s_cst[c + 1] > s_cst[c];
        s_ckey[c] = ne ? ((unsigned long long)0x7f800000u << 32) : 0ull;
        s_cubp[((c & 15) << 5) | (c >> 4)] = ne ? INF : 0.0f;
    }
    if (lane == 0) g_idx[0] = 0;
    float4 q0 = g_pos4[0];
    float qx = q0.x, qy = q0.y, qz = q0.z;
    __syncwarp();

    // per-lane constant cell geometry: lane owns cells [lane*16, lane*16+16)
    const float cx0 = (float)(lane >> 2) * 0.125f;
    const float cy0 = (float)((2 * lane) & 7) * 0.125f;
    const float cy1 = (float)((2 * lane + 1) & 7) * 0.125f;
    const float cz0 = (float)(lane & 7) * 0.125f;
    const int cbase = lane << 4;

    for (int t = 0; t < Mm - 1; ++t) {
        // ---- phase 1: activity scan over 512 cells ----
        float dv = fmaxf(fmaxf(cx0 - qx, qx - (cx0 + 0.125f)), 0.0f);
        float dx2 = dv * dv;
        float dya = fmaxf(fmaxf(cy0 - qy, qy - (cy0 + 0.125f)), 0.0f); dya *= dya;
        float dyb = fmaxf(fmaxf(cy1 - qy, qy - (cy1 + 0.125f)), 0.0f); dyb *= dyb;
        float dzl = fmaxf(fmaxf(cz0 - qz, qz - (cz0 + 0.125f)), 0.0f); dzl *= dzl;
        float dz2[8];
        #pragma unroll
        for (int k = 0; k < 8; ++k) dz2[k] = __shfl_sync(FULL, dzl, k);
        unsigned amask = 0;
        #pragma unroll
        for (int j = 0; j < 16; ++j) {
            float lb2 = dx2 + (j < 8 ? dya : dyb) + dz2[j & 7];
            float cub = s_cubp[(j << 5) | lane];     // conflict-free
            if (lb2 * 0.99999f < cub) amask |= (1u << j);
        }
        int cnt = __popc(amask);
        int pre = cnt;
        #pragma unroll
        for (int o = 1; o < 32; o <<= 1) {
            int v = __shfl_up_sync(FULL, pre, o);
            if (lane >= o) pre += v;
        }
        int nact = __shfl_sync(FULL, pre, 31);
        pre -= cnt;
        unsigned mm = amask;
        int w = pre;
        while (mm) { int j = __ffs(mm) - 1; mm &= mm - 1; s_act[w++] = cbase + j; }
        __syncwarp();

        // ---- phase 2: update active cells; per-lane partials, parallel reduce ----
        for (int a0 = 0; a0 < nact; a0 += 32) {
            int ab = min(32, nact - a0);
            for (int a = 0; a < ab; ++a) {
                int cid = s_act[a0 + a];
                int st = s_cst[cid], en = s_cst[cid + 1];
                float bv = -1.0f; int bidx = 0x7FFFFFFF;
                float bx = 0.f, by = 0.f, bz = 0.f;
                for (int i = st + lane; i < en; i += 32) {
                    float4 p = __ldg(&sp[i]);
                    float ddx = p.x - qx, ddy = p.y - qy, ddz = p.z - qz;
                    float d2 = __fadd_rn(__fadd_rn(__fmul_rn(ddx, ddx),
                                                   __fmul_rn(ddy, ddy)),
                                         __fmul_rn(ddz, ddz));
                    float nm = fminf(s_mind[i], d2);
                    s_mind[i] = nm;
                    int oi = __float_as_int(p.w);
                    if (nm > bv || (nm == bv && oi < bidx)) {
                        bv = nm; bidx = oi; bx = p.x; by = p.y; bz = p.z;
                    }
                }
                unsigned long long bk = (bv < 0.f) ? 0ull :
                    (((unsigned long long)__float_as_uint(bv) << 32) |
                     (unsigned long long)(0xFFFFFFFFu - (unsigned)bidx));
                s_pkey[a * 33 + lane] = bk;                  // padded stride
                s_ppos[a * 33 + lane] = make_float4(bx, by, bz, 0.f);
            }
            __syncwarp();
            if (lane < ab) {                                 // one lane per cell
                unsigned long long best = 0ull; int bj = 0;
                #pragma unroll 8
                for (int j = 0; j < 32; ++j) {
                    unsigned long long k = s_pkey[lane * 33 + j];
                    if (k > best) { best = k; bj = j; }
                }
                int cid = s_act[a0 + lane];
                s_ckey[cid] = best;
                s_cubp[((cid & 15) << 5) | (cid >> 4)] =
                    __uint_as_float((unsigned)(best >> 32));
                s_winpos[cid] = s_ppos[lane * 33 + bj];
            }
            __syncwarp();
        }

        // ---- phase 3: global argmax over 512 cached keys ----
        unsigned long long best = 0ull; int bc = 0;
        #pragma unroll
        for (int j = 0; j < 16; ++j) {
            unsigned long long k = s_ckey[lane | (j << 5)];
            if (k > best) { best = k; bc = lane | (j << 5); }
        }
        unsigned hi = (unsigned)(best >> 32), lo = (unsigned)best;
        unsigned mhi = __reduce_max_sync(FULL, hi);
        unsigned lo2 = (hi == mhi) ? lo : 0u;
        unsigned mlo = __reduce_max_sync(FULL, lo2);
        bool win = (hi == mhi) && (lo == mlo);               // unique (idx in lo)
        int wl = __ffs(__ballot_sync(FULL, win)) - 1;
        float nqx = 0.f, nqy = 0.f, nqz = 0.f;
        if (win) {
            float4 wp = s_winpos[bc];
            nqx = wp.x; nqy = wp.y; nqz = wp.z;
            g_idx[t + 1] = (int)(0xFFFFFFFFu - mlo);
        }
        qx = __shfl_sync(FULL, nqx, wl);
        qy = __shfl_sync(FULL, nqy, wl);
        qz = __shfl_sync(FULL, nqz, wl);
    }
}

// ---------------- selection map ----------------
__global__ void sel_init_kernel() {
    int i = blockIdx.x * blockDim.x + threadIdx.x;
    if (i < Nn) g_selmap[i] = -1;
    if (i < Mm) g_ecnt[i] = 0;
}
__global__ void sel_set_kernel() {
    int m = blockIdx.x * blockDim.x + threadIdx.x;
    if (m < Mm) g_selmap[g_idx[m]] = m;
}

// ---------------- CSR build over selected-dst edges ----------------
__global__ void edge_hist_kernel(const int* __restrict__ ei) {
    int e = blockIdx.x * blockDim.x + threadIdx.x;
    if (e >= Ee) return;
    int c = g_selmap[ei[Ee + e]];
    if (c >= 0) atomicAdd(&g_ecnt[c], 1);
}
__global__ void edge_scan_kernel() {
    __shared__ int sh[1024];
    int tid = threadIdx.x;
    int c[5]; int s = 0;
    #pragma unroll
    for (int j = 0; j < 5; ++j) {
        int m = tid * 5 + j;
        c[j] = (m < Mm) ? g_ecnt[m] : 0;
        s += c[j];
    }
    sh[tid] = s;
    __syncthreads();
    for (int o = 1; o < 1024; o <<= 1) {
        int v = (tid >= o) ? sh[tid - o] : 0;
        __syncthreads();
        sh[tid] += v;
        __syncthreads();
    }
    int ex = (tid > 0) ? sh[tid - 1] : 0;
    #pragma unroll
    for (int j = 0; j < 5; ++j) {
        int m = tid * 5 + j;
        if (m < Mm) { g_eoff[m] = ex; g_efill[m] = ex; ex += c[j]; }
    }
}
__global__ void edge_fill_kernel(const int* __restrict__ ei) {
    int e = blockIdx.x * blockDim.x + threadIdx.x;
    if (e >= Ee) return;
    int c = g_selmap[ei[Ee + e]];
    if (c >= 0) {
        int p = atomicAdd(&g_efill[c], 1);
        g_elist[p] = e;
    }
}

// ---------------- spline accumulate: block per node, SMEM tile, no atomics ----------------
#define CHK 64
__global__ void __launch_bounds__(64) spline_node_kernel(const float* __restrict__ x,
                                                         const int*   __restrict__ ei,
                                                         const float* __restrict__ ea) {
    __shared__ float sacc[PIN];
    __shared__ int   s_src[CHK];
    __shared__ float s_v[CHK][3];
    __shared__ float s_xj[CHK][KIN];
    int m = blockIdx.x, o = threadIdx.x;
    #pragma unroll
    for (int k = o; k < PIN; k += 64) sacc[k] = 0.f;
    int st = g_eoff[m], cnt = g_ecnt[m];

    for (int c0 = 0; c0 < cnt; c0 += CHK) {
        int ce = min(CHK, cnt - c0);
        __syncthreads();
        int k = c0 + o;
        if (k < cnt) {
            int e = __ldg(&g_elist[st + k]);
            s_src[o]  = __ldg(&ei[e]);
            s_v[o][0] = __ldg(&ea[3 * e]);
            s_v[o][1] = __ldg(&ea[3 * e + 1]);
            s_v[o][2] = __ldg(&ea[3 * e + 2]);
        }
        __syncthreads();
        for (int idx = o; idx < ce * KIN; idx += 64) {
            int j = idx >> 6, f = idx & 63;
            s_xj[j][f] = __ldg(&x[(size_t)s_src[j] * KIN + f]);
        }
        __syncthreads();
        for (int j = 0; j < ce; ++j) {
            float v0 = __fmul_rn(s_v[j][0], 2.0f);
            float v1 = __fmul_rn(s_v[j][1], 2.0f);
            float v2 = __fmul_rn(s_v[j][2], 2.0f);
            float k0 = fminf(fmaxf(floorf(v0), 0.f), 1.f);
            float k1 = fminf(fmaxf(floorf(v1), 0.f), 1.f);
            float k2 = fminf(fmaxf(floorf(v2), 0.f), 1.f);
            float f0 = v0 - k0, f1 = v1 - k1, f2 = v2 - k2;
            int pb = (int)k0 * 9 + (int)k1 * 3 + (int)k2;
            float xj = s_xj[j][o];
            float* ab = sacc + pb * KIN + o;
            #pragma unroll
            for (int s = 0; s < 8; ++s) {
                int b0 = s & 1, b1 = (s >> 1) & 1, b2 = (s >> 2) & 1;
                float b = b0 ? f0 : (1.0f - f0);
                b = __fmul_rn(b, b1 ? f1 : (1.0f - f1));
                b = __fmul_rn(b, b2 ? f2 : (1.0f - f2));
                int off = (b0 * 9 + b1 * 3 + b2) * KIN;
                ab[off] += __fmul_rn(b, xj);
            }
        }
    }
    __syncthreads();
    size_t baseo = (size_t)m * PIN;
    #pragma unroll
    for (int k = o; k < PIN; k += 64) g_acc[baseo + k] = sacc[k];
}

// ---------------- GEMM + root + bias + ELU (16 nodes per block) ----------------
__global__ void node_out_kernel(const float* __restrict__ x,
                                const float* __restrict__ W,
                                const float* __restrict__ rootw,
                                const float* __restrict__ bias,
                                float* __restrict__ out) {
    int m0 = blockIdx.x * 16;
    int o  = threadIdx.x;
    const float* a = g_acc + (size_t)m0 * PIN;
    float s[16];
    #pragma unroll
    for (int j = 0; j < 16; ++j) s[j] = 0.f;
    #pragma unroll 4
    for (int k = 0; k < PIN; ++k) {
        float w = __ldg(&W[k * KIN + o]);
        #pragma unroll
        for (int j = 0; j < 16; ++j)
            s[j] += __ldg(&a[(size_t)j * PIN + k]) * w;   // padded g_acc: safe
    }
    float b = bias[o];
    for (int j = 0; j < 16; ++j) {
        int m = m0 + j;
        if (m >= Mm) break;
        float v = s[j] / fmaxf((float)g_ecnt[m], 1.0f);
        int node = g_idx[m];
        const float* xr = x + (size_t)node * KIN;
        #pragma unroll 8
        for (int i = 0; i < KIN; ++i)
            v += __ldg(&xr[i]) * __ldg(&rootw[i * KIN + o]);
        v += b;
        v = (v > 0.f) ? v : expm1f(v);
        out[SEC_X + m * KIN + o] = v;
    }
}

// ---------------- radius: grid candidates + bitmap, ordered emit ----------------
#define RW 625
__global__ void __launch_bounds__(128) radius_kernel(float* __restrict__ out) {
    __shared__ unsigned s_bm[RW];
    __shared__ int s_cells[32];
    __shared__ int s_ncell;
    int m = blockIdx.x, tid = threadIdx.x;
    int node = g_idx[m];
    float4 q = g_pos4[node];
    for (int i = tid; i < RW; i += 128) s_bm[i] = 0u;
    if (tid == 0) {
        int lo[3], hi[3];
        float qc[3] = {q.x, q.y, q.z};
        for (int d = 0; d < 3; ++d) {
            lo[d] = max(0, (int)floorf((qc[d] - 0.1f) * 8.0f - 1e-3f));
            hi[d] = min(7, (int)floorf((qc[d] + 0.1f) * 8.0f + 1e-3f));
        }
        int n = 0;
        for (int cx = lo[0]; cx <= hi[0]; ++cx)
            for (int cy = lo[1]; cy <= hi[1]; ++cy)
                for (int cz = lo[2]; cz <= hi[2]; ++cz)
                    s_cells[n++] = (cx << 6) | (cy << 3) | cz;
        s_ncell = n;
    }
    __syncthreads();
    int nc = s_ncell;
    for (int ci = 0; ci < nc; ++ci) {
        int cid = s_cells[ci];
        int st = g_cellstart[cid], en = g_cellstart[cid + 1];
        for (int i = st + tid; i < en; i += 128) {
            float4 p = __ldg(&g_spos[i]);
            float an = __fadd_rn(__fadd_rn(__fmul_rn(p.x, p.x), __fmul_rn(p.y, p.y)),
                                 __fmul_rn(p.z, p.z));
            float dot = __fadd_rn(__fadd_rn(__fmul_rn(q.x, p.x), __fmul_rn(q.y, p.y)),
                                  __fmul_rn(q.z, p.z));
            float d2 = __fadd_rn(__fadd_rn(q.w, an), -__fmul_rn(2.0f, dot));
            if (d2 < R2c) {
                int oi = __float_as_int(p.w);
                atomicOr(&s_bm[oi >> 5], 1u << (oi & 31));
            }
        }
    }
    __syncthreads();
    if (tid < 32) {
        int lane = tid;
        int base = 0;
        for (int w0 = 0; w0 < RW; w0 += 32) {
            unsigned word = (w0 + lane < RW) ? s_bm[w0 + lane] : 0u;
            int pc = __popc(word);
            int ex = pc;
            #pragma unroll
            for (int o = 1; o < 32; o <<= 1) {
                int v = __shfl_up_sync(0xffffffffu, ex, o);
                if (lane >= o) ex += v;
            }
            int tot = __shfl_sync(0xffffffffu, ex, 31);
            ex -= pc;
            int pos = base + ex;
            while (word && pos < MAXNb) {
                int b = __ffs(word) - 1;
                word &= word - 1;
                int oi = (w0 + lane) * 32 + b;
                out[SEC_COL + m * MAXNb + pos] = (float)oi;
                out[SEC_ROW + m * MAXNb + pos] = (float)m;
                ++pos;
            }
            base += tot;
            if (base >= MAXNb) break;
        }
        for (int j = base + lane; j < MAXNb; j += 32) {
            out[SEC_COL + m * MAXNb + j] = -1.0f;
            out[SEC_ROW + m * MAXNb + j] = -1.0f;
        }
    }
}

// ---------------- tail gathers ----------------
__global__ void tail_kernel(const float* __restrict__ pos,
                            const float* __restrict__ ea,
                            float* __restrict__ out) {
    int m = blockIdx.x * blockDim.x + threadIdx.x;
    if (m >= Mm) return;
    int node = g_idx[m];
    out[SEC_POS + 3 * m + 0] = pos[3 * node + 0];
    out[SEC_POS + 3 * m + 1] = pos[3 * node + 1];
    out[SEC_POS + 3 * m + 2] = pos[3 * node + 2];
    out[SEC_BATCH + m]       = 0.0f;
    out[SEC_EA + 3 * m + 0]  = ea[3 * node + 0];
    out[SEC_EA + 3 * m + 1]  = ea[3 * node + 1];
    out[SEC_EA + 3 * m + 2]  = ea[3 * node + 2];
}

// ---------------- launch ----------------
extern "C" void kernel_launch(void* const* d_in, const int* in_sizes, int n_in,
                              void* d_out, int out_size) {
    const float* x     = (const float*)d_in[0];
    const int*   ei    = (const int*)d_in[1];
    const float* ea    = (const float*)d_in[2];
    const float* pos   = (const float*)d_in[3];
    const float* W     = (const float*)d_in[5];
    const float* rootw = (const float*)d_in[6];
    const float* bias  = (const float*)d_in[7];
    float* out = (float*)d_out;

    cudaFuncSetAttribute(fps_kernel, cudaFuncAttributeMaxDynamicSharedMemorySize,
                         FPS_SMEM);

    prep1b_kernel<<<1, 1024>>>(pos);                 // launch 1
    cell_scan_kernel<<<1, NC>>>();                   // launch 2
    cell_scatter_kernel<<<(Nn + 255) / 256, 256>>>(pos); // launch 3
    fps_kernel<<<1, 32, FPS_SMEM>>>();               // launch 4  (ncu target)

    sel_init_kernel<<<(Nn + 255) / 256, 256>>>();
    sel_set_kernel<<<(Mm + 255) / 256, 256>>>();
    edge_hist_kernel<<<(Ee + 255) / 256, 256>>>(ei);
    edge_scan_kernel<<<1, 1024>>>();
    edge_fill_kernel<<<(Ee + 255) / 256, 256>>>(ei);

    spline_node_kernel<<<Mm, 64>>>(x, ei, ea);
    node_out_kernel<<<(Mm + 15) / 16, KIN>>>(x, W, rootw, bias, out);
    radius_kernel<<<Mm, 128>>>(out);
    tail_kernel<<<(Mm + 127) / 128, 128>>>(pos, ea, out);
}

// round 6
// speedup vs baseline: 3.1847x; 3.1847x over previous
#include <cuda_runtime.h>
#include <math.h>

// ---------------- problem constants ----------------
#define Nn    20000
#define Ee    640000
#define Pp    27
#define Mm    5000
#define MAXNb 64
#define KIN   64
#define PIN   (Pp * KIN)      // 1728
#define R2c   0.01f
#define NC    512             // 8x8x8 spatial cells

// output section offsets (flattened float32 tuple concat)
#define SEC_X     0
#define SEC_COL   320000
#define SEC_ROW   640000
#define SEC_POS   960000
#define SEC_BATCH 975000
#define SEC_EA    980000

// ---------------- persistent device scratch ----------------
__device__ __align__(16) float4 g_pos4[Nn];   // x,y,z, |p|^2
__device__ int    g_idx[Mm];
__device__ int    g_pcell[Nn];
__device__ int    g_cellcnt[NC];
__device__ int    g_cellstart[NC + 1];
__device__ int    g_cellfill[NC];
__device__ __align__(16) float4 g_spos[Nn];   // cell-sorted: x,y,z, orig idx bits
__device__ __align__(16) float g_accN[(size_t)Nn * PIN];  // 138 MB, all nodes
__device__ float  g_degN[Nn];

// ---------------- launch 1: pos4 + cell id + histogram (single block) ----------------
__global__ void __launch_bounds__(1024) prep1b_kernel(const float* __restrict__ pos) {
    int tid = threadIdx.x;
    if (tid < NC) g_cellcnt[tid] = 0;
    __syncthreads();
    for (int i = tid; i < Nn; i += 1024) {
        float x = pos[3 * i], y = pos[3 * i + 1], z = pos[3 * i + 2];
        float an = __fadd_rn(__fadd_rn(__fmul_rn(x, x), __fmul_rn(y, y)),
                             __fmul_rn(z, z));
        g_pos4[i] = make_float4(x, y, z, an);
        int cx = min((int)(x * 8.0f), 7);
        int cy = min((int)(y * 8.0f), 7);
        int cz = min((int)(z * 8.0f), 7);
        int cid = (cx << 6) | (cy << 3) | cz;
        g_pcell[i] = cid;
        atomicAdd(&g_cellcnt[cid], 1);
    }
}

// ---------------- launch 2: exclusive scan of cell counts ----------------
__global__ void cell_scan_kernel() {
    __shared__ int sh[NC];
    int tid = threadIdx.x;
    int v = g_cellcnt[tid];
    sh[tid] = v;
    __syncthreads();
    for (int o = 1; o < NC; o <<= 1) {
        int t = (tid >= o) ? sh[tid - o] : 0;
        __syncthreads();
        sh[tid] += t;
        __syncthreads();
    }
    g_cellstart[tid + 1] = sh[tid];
    g_cellfill[tid] = sh[tid] - v;
    if (tid == 0) g_cellstart[0] = 0;
}

// ---------------- launch 3: cell scatter + zero acc/deg (fused) ----------------
#define ZB 33750   // 33750*256 float4 = Nn*PIN floats
__global__ void scatter_zero_kernel(const float* __restrict__ pos) {
    int i = blockIdx.x * blockDim.x + threadIdx.x;
    if (i < Nn) {
        int cid = g_pcell[i];
        int off = atomicAdd(&g_cellfill[cid], 1);
        g_spos[off] = make_float4(pos[3 * i], pos[3 * i + 1], pos[3 * i + 2],
                                  __int_as_float(i));
        g_degN[i] = 0.0f;
    }
    reinterpret_cast<float4*>(g_accN)[i] = make_float4(0.f, 0.f, 0.f, 0.f);
}

// ---------------- FPS body: 512 threads, 3 barriers/iter, exact pruning ----------------
#define OFF_UB     80000u
#define OFF_KLO    82048u
#define OFF_WPOS   84096u
#define OFF_CST    92288u
#define OFF_ACT    94340u
#define OFF_NACT   96388u
#define OFF_GQ     96392u
#define FPS_SMEM   96416u

__device__ void fps512(unsigned char* s_raw) {
    float*    s_mind = (float*)(s_raw);
    float*    s_ub   = (float*)(s_raw + OFF_UB);
    unsigned* s_klo  = (unsigned*)(s_raw + OFF_KLO);
    float4*   s_wp   = (float4*)(s_raw + OFF_WPOS);
    int*      s_cst  = (int*)(s_raw + OFF_CST);
    int*      s_act  = (int*)(s_raw + OFF_ACT);
    int*      s_nact = (int*)(s_raw + OFF_NACT);
    float*    s_gq   = (float*)(s_raw + OFF_GQ);

    const int tid = threadIdx.x, lane = tid & 31, wid = tid >> 5;
    const unsigned FULL = 0xffffffffu;
    const float INF = __int_as_float(0x7f800000);

    for (int i = tid; i < Nn; i += 512) s_mind[i] = INF;
    for (int i = tid; i <= NC; i += 512) s_cst[i] = g_cellstart[i];  // covers [0,512]
    __syncthreads();
    if (tid < NC) {
        bool ne = s_cst[tid + 1] > s_cst[tid];
        s_ub[tid] = ne ? INF : 0.0f;
        s_klo[tid] = 0u;
    }
    if (tid == 0) { *s_nact = 0; g_idx[0] = 0; }
    float4 q0 = g_pos4[0];
    float qx = q0.x, qy = q0.y, qz = q0.z;
    // this thread's cell geometry (tid == cell id for tid < NC)
    const float lx = (float)(tid >> 6) * 0.125f;
    const float ly = (float)((tid >> 3) & 7) * 0.125f;
    const float lz = (float)(tid & 7) * 0.125f;
    __syncthreads();

    for (int t = 0; t < Mm - 1; ++t) {
        // ---- phase 1: one cell per thread, ballot compaction ----
        float dx = fmaxf(fmaxf(lx - qx, qx - (lx + 0.125f)), 0.0f);
        float dy = fmaxf(fmaxf(ly - qy, qy - (ly + 0.125f)), 0.0f);
        float dz = fmaxf(fmaxf(lz - qz, qz - (lz + 0.125f)), 0.0f);
        float lb2 = dx * dx + dy * dy + dz * dz;
        bool act = (tid < NC) && (lb2 * 0.99999f < s_ub[tid]);
        unsigned bal = __ballot_sync(FULL, act);
        int base = 0;
        if (lane == 0 && bal) base = atomicAdd(s_nact, __popc(bal));
        base = __shfl_sync(FULL, base, 0);
        if (act) s_act[base + __popc(bal & ((1u << lane) - 1u))] = tid;
        __syncthreads();                              // S0
        // ---- phase 2: active cells distributed over 16 warps ----
        int nact = *s_nact;
        for (int a = wid; a < nact; a += 16) {
            int cid = s_act[a];
            int st = s_cst[cid];
            int en = min(s_cst[cid + 1], Nn);
            float bv = -1.0f; int bidx = 0x7FFFFFFF;
            float bx = 0.f, by = 0.f, bz = 0.f;
            for (int i = st + lane; i < en; i += 32) {
                float4 p = __ldg(&g_spos[i]);
                float ddx = p.x - qx, ddy = p.y - qy, ddz = p.z - qz;
                float d2 = __fadd_rn(__fadd_rn(__fmul_rn(ddx, ddx),
                                               __fmul_rn(ddy, ddy)),
                                     __fmul_rn(ddz, ddz));
                float nm = fminf(s_mind[i], d2);
                s_mind[i] = nm;
                int oi = __float_as_int(p.w);
                if (nm > bv || (nm == bv && oi < bidx)) {
                    bv = nm; bidx = oi; bx = p.x; by = p.y; bz = p.z;
                }
            }
            unsigned vb = (bv < 0.f) ? 0u : __float_as_uint(bv);
            unsigned mv = __reduce_max_sync(FULL, vb);
            unsigned ci = (vb == mv) ? (unsigned)bidx : 0xFFFFFFFFu;
            unsigned mi = __reduce_min_sync(FULL, ci);
            if (vb == mv && (unsigned)bidx == mi) {   // unique winner lane
                s_ub[cid]  = __uint_as_float(mv);
                s_klo[cid] = 0xFFFFFFFFu - mi;
                s_wp[cid]  = make_float4(bx, by, bz, 0.f);
            }
        }
        __syncthreads();                              // S1
        // ---- phase 3: warp 0 scans 512 cached keys ----
        if (wid == 0) {
            if (lane == 0) *s_nact = 0;
            unsigned long long best = 0ull; int bc = 0;
            #pragma unroll
            for (int j = 0; j < 16; ++j) {
                int c = lane + (j << 5);
                unsigned long long k =
                    ((unsigned long long)__float_as_uint(s_ub[c]) << 32) |
                    (unsigned long long)s_klo[c];
                if (k > best) { best = k; bc = c; }
            }
            unsigned hi = (unsigned)(best >> 32), lo = (unsigned)best;
            unsigned mhi = __reduce_max_sync(FULL, hi);
            unsigned lo2 = (hi == mhi) ? lo : 0u;
            unsigned mlo = __reduce_max_sync(FULL, lo2);
            if (hi == mhi && lo == mlo) {             // unique (lo embeds idx)
                float4 wp = s_wp[bc];
                s_gq[0] = wp.x; s_gq[1] = wp.y; s_gq[2] = wp.z;
                g_idx[t + 1] = (int)(0xFFFFFFFFu - mlo);
            }
        }
        __syncthreads();                              // S2
        qx = s_gq[0]; qy = s_gq[1]; qz = s_gq[2];
    }
}

// ---------------- scatter body: all edges, all nodes, warp per edge ----------------
__device__ void scatter_all(const float* __restrict__ x,
                            const int*   __restrict__ ei,
                            const float* __restrict__ ea,
                            int cta, int nctas) {
    int lane = threadIdx.x & 31;
    int gw   = cta * 16 + (threadIdx.x >> 5);
    int nw   = nctas * 16;
    for (int e = gw; e < Ee; e += nw) {
        int dst = __ldg(&ei[Ee + e]);
        int src = __ldg(&ei[e]);
        float v0 = __fmul_rn(__ldg(&ea[3 * e + 0]), 2.0f);
        float v1 = __fmul_rn(__ldg(&ea[3 * e + 1]), 2.0f);
        float v2 = __fmul_rn(__ldg(&ea[3 * e + 2]), 2.0f);
        float k0 = fminf(fmaxf(floorf(v0), 0.f), 1.f);
        float k1 = fminf(fmaxf(floorf(v1), 0.f), 1.f);
        float k2 = fminf(fmaxf(floorf(v2), 0.f), 1.f);
        float f0 = v0 - k0, f1 = v1 - k1, f2 = v2 - k2;
        int pb = (int)k0 * 9 + (int)k1 * 3 + (int)k2;
        float xj0 = __ldg(&x[(size_t)src * KIN + lane]);
        float xj1 = __ldg(&x[(size_t)src * KIN + 32 + lane]);
        float* accb = g_accN + (size_t)dst * PIN;
        #pragma unroll
        for (int s = 0; s < 8; ++s) {
            int b0 = s & 1, b1 = (s >> 1) & 1, b2 = (s >> 2) & 1;
            float b = b0 ? f0 : (1.0f - f0);
            b = __fmul_rn(b, b1 ? f1 : (1.0f - f1));
            b = __fmul_rn(b, b2 ? f2 : (1.0f - f2));
            int off = (pb + b0 * 9 + b1 * 3 + b2) * KIN;
            atomicAdd(&accb[off + lane],      __fmul_rn(b, xj0));
            atomicAdd(&accb[off + 32 + lane], __fmul_rn(b, xj1));
        }
        if (lane == 0) atomicAdd(&g_degN[dst], 1.0f);
    }
}

// ---------------- launch 4 (FAT): CTA0 = FPS, CTA1..147 = scatter ----------------
__global__ void __launch_bounds__(512, 1) fat_kernel(const float* __restrict__ x,
                                                     const int*   __restrict__ ei,
                                                     const float* __restrict__ ea) {
    extern __shared__ unsigned char s_raw[];
    if (blockIdx.x == 0) fps512(s_raw);
    else scatter_all(x, ei, ea, blockIdx.x - 1, gridDim.x - 1);
}

// ---------------- launch 5: gather-GEMM + root + bias + ELU (20 nodes/block) ----------------
#define NB 20
__global__ void __launch_bounds__(64) node_out_kernel(const float* __restrict__ x,
                                                      const float* __restrict__ W,
                                                      const float* __restrict__ rootw,
                                                      const float* __restrict__ bias,
                                                      float* __restrict__ out) {
    int m0 = blockIdx.x * NB;
    int o  = threadIdx.x;
    int nodes[NB];
    #pragma unroll
    for (int j = 0; j < NB; ++j) nodes[j] = g_idx[m0 + j];
    float s[NB];
    #pragma unroll
    for (int j = 0; j < NB; ++j) s[j] = 0.f;
    #pragma unroll 2
    for (int k = 0; k < PIN; ++k) {
        float w = __ldg(&W[k * KIN + o]);
        #pragma unroll
        for (int j = 0; j < NB; ++j)
            s[j] += __ldg(&g_accN[(size_t)nodes[j] * PIN + k]) * w;
    }
    float b = bias[o];
    for (int j = 0; j < NB; ++j) {
        int m = m0 + j;
        float v = s[j] / fmaxf(g_degN[nodes[j]], 1.0f);
        const float* xr = x + (size_t)nodes[j] * KIN;
        #pragma unroll 8
        for (int i = 0; i < KIN; ++i)
            v += __ldg(&xr[i]) * __ldg(&rootw[i * KIN + o]);
        v += b;
        v = (v > 0.f) ? v : expm1f(v);
        out[SEC_X + m * KIN + o] = v;
    }
}

// ---------------- launch 6: radius via grid + bitmap, ordered emit ----------------
#define RW 625
__global__ void __launch_bounds__(128) radius_kernel(float* __restrict__ out) {
    __shared__ unsigned s_bm[RW];
    __shared__ int s_cells[32];
    __shared__ int s_ncell;
    int m = blockIdx.x, tid = threadIdx.x;
    int node = g_idx[m];
    float4 q = g_pos4[node];
    for (int i = tid; i < RW; i += 128) s_bm[i] = 0u;
    if (tid == 0) {
        int lo[3], hi[3];
        float qc[3] = {q.x, q.y, q.z};
        for (int d = 0; d < 3; ++d) {
            lo[d] = max(0, (int)floorf((qc[d] - 0.1f) * 8.0f - 1e-3f));
            hi[d] = min(7, (int)floorf((qc[d] + 0.1f) * 8.0f + 1e-3f));
        }
        int n = 0;
        for (int cx = lo[0]; cx <= hi[0]; ++cx)
            for (int cy = lo[1]; cy <= hi[1]; ++cy)
                for (int cz = lo[2]; cz <= hi[2]; ++cz)
                    s_cells[n++] = (cx << 6) | (cy << 3) | cz;
        s_ncell = n;
    }
    __syncthreads();
    int nc = s_ncell;
    for (int ci = 0; ci < nc; ++ci) {
        int cid = s_cells[ci];
        int st = g_cellstart[cid], en = g_cellstart[cid + 1];
        for (int i = st + tid; i < en; i += 128) {
            float4 p = __ldg(&g_spos[i]);
            float an = __fadd_rn(__fadd_rn(__fmul_rn(p.x, p.x), __fmul_rn(p.y, p.y)),
                                 __fmul_rn(p.z, p.z));
            float dot = __fadd_rn(__fadd_rn(__fmul_rn(q.x, p.x), __fmul_rn(q.y, p.y)),
                                  __fmul_rn(q.z, p.z));
            float d2 = __fadd_rn(__fadd_rn(q.w, an), -__fmul_rn(2.0f, dot));
            if (d2 < R2c) {
                int oi = __float_as_int(p.w);
                atomicOr(&s_bm[oi >> 5], 1u << (oi & 31));
            }
        }
    }
    __syncthreads();
    if (tid < 32) {
        int lane = tid;
        int base = 0;
        for (int w0 = 0; w0 < RW; w0 += 32) {
            unsigned word = (w0 + lane < RW) ? s_bm[w0 + lane] : 0u;
            int pc = __popc(word);
            int ex = pc;
            #pragma unroll
            for (int o = 1; o < 32; o <<= 1) {
                int v = __shfl_up_sync(0xffffffffu, ex, o);
                if (lane >= o) ex += v;
            }
            int tot = __shfl_sync(0xffffffffu, ex, 31);
            ex -= pc;
            int pos = base + ex;
            while (word && pos < MAXNb) {
                int b = __ffs(word) - 1;
                word &= word - 1;
                int oi = (w0 + lane) * 32 + b;
                out[SEC_COL + m * MAXNb + pos] = (float)oi;
                out[SEC_ROW + m * MAXNb + pos] = (float)m;
                ++pos;
            }
            base += tot;
            if (base >= MAXNb) break;
        }
        for (int j = base + lane; j < MAXNb; j += 32) {
            out[SEC_COL + m * MAXNb + j] = -1.0f;
            out[SEC_ROW + m * MAXNb + j] = -1.0f;
        }
    }
}

// ---------------- launch 7: tail gathers ----------------
__global__ void tail_kernel(const float* __restrict__ pos,
                            const float* __restrict__ ea,
                            float* __restrict__ out) {
    int m = blockIdx.x * blockDim.x + threadIdx.x;
    if (m >= Mm) return;
    int node = g_idx[m];
    out[SEC_POS + 3 * m + 0] = pos[3 * node + 0];
    out[SEC_POS + 3 * m + 1] = pos[3 * node + 1];
    out[SEC_POS + 3 * m + 2] = pos[3 * node + 2];
    out[SEC_BATCH + m]       = 0.0f;
    out[SEC_EA + 3 * m + 0]  = ea[3 * node + 0];
    out[SEC_EA + 3 * m + 1]  = ea[3 * node + 1];
    out[SEC_EA + 3 * m + 2]  = ea[3 * node + 2];
}

// ---------------- launch ----------------
extern "C" void kernel_launch(void* const* d_in, const int* in_sizes, int n_in,
                              void* d_out, int out_size) {
    const float* x     = (const float*)d_in[0];
    const int*   ei    = (const int*)d_in[1];
    const float* ea    = (const float*)d_in[2];
    const float* pos   = (const float*)d_in[3];
    const float* W     = (const float*)d_in[5];
    const float* rootw = (const float*)d_in[6];
    const float* bias  = (const float*)d_in[7];
    float* out = (float*)d_out;

    cudaFuncSetAttribute(fat_kernel, cudaFuncAttributeMaxDynamicSharedMemorySize,
                         FPS_SMEM);

    prep1b_kernel<<<1, 1024>>>(pos);                 // 1
    cell_scan_kernel<<<1, NC>>>();                   // 2
    scatter_zero_kernel<<<ZB, 256>>>(pos);           // 3
    fat_kernel<<<148, 512, FPS_SMEM>>>(x, ei, ea);   // 4  (ncu target)
    node_out_kernel<<<Mm / NB, KIN>>>(x, W, rootw, bias, out); // 5
    radius_kernel<<<Mm, 128>>>(out);                 // 6
    tail_kernel<<<(Mm + 127) / 128, 128>>>(pos, ea, out);      // 7
}